// round 7
// baseline (speedup 1.0000x reference)
#include <cuda_runtime.h>

#define TT 2048
#define DD 64
#define HH 64
#define NG 256   // 4*H gates
#define BB_TOT 256

// 512 MB scratch: precomputed input projections xg[b][t][g] (bias included)
__device__ float g_xg[(size_t)BB_TOT * TT * NG];

// Packed fp32x2 FMA (sm_100+): d = a*b + c on two packed floats.
__device__ __forceinline__ unsigned long long ffma2(unsigned long long a,
                                                    unsigned long long b,
                                                    unsigned long long c) {
    unsigned long long d;
    asm("fma.rn.f32x2 %0, %1, %2, %3;" : "=l"(d) : "l"(a), "l"(b), "l"(c));
    return d;
}

__device__ __forceinline__ float red2(unsigned long long v) {
    float lo, hi;
    asm("mov.b64 {%0, %1}, %2;" : "=f"(lo), "=f"(hi) : "l"(v));
    return lo + hi;
}

// HW tanh: single MUFU op (sm_75+), ~16 cyc, abs err ~1e-5
__device__ __forceinline__ float tanh_ap(float x) {
    float y;
    asm("tanh.approx.f32 %0, %1;" : "=f"(y) : "f"(x));
    return y;
}

// ---------------------------------------------------------------------------
// Kernel 1 (unchanged from R6, measured ~380us): xg = bias + W_ih . x
// ---------------------------------------------------------------------------
__global__ void __launch_bounds__(256, 1)
xg_gemm(const float* __restrict__ x, const float* __restrict__ w_ih,
        const float* __restrict__ b_ih, const float* __restrict__ b_hh,
        int nrows)
{
    __shared__ __align__(16) float xs[2][32][DD];   // 2 x 8KB tiles

    const int tid  = threadIdx.x;
    const int tg   = tid & 127;       // gate pair: gates 2tg, 2tg+1
    const int half = tid >> 7;        // rows 0..15 or 16..31
    const int g0   = 2 * tg;

    ulonglong2 wa[16], wb[16];
    {
        const ulonglong2* pa = (const ulonglong2*)(w_ih + (size_t)g0 * DD);
        const ulonglong2* pb = (const ulonglong2*)(w_ih + (size_t)(g0 + 1) * DD);
#pragma unroll
        for (int j = 0; j < 16; ++j) { wa[j] = pa[j]; wb[j] = pb[j]; }
    }
    const float ba = b_ih[g0] + b_hh[g0];
    const float bb = b_ih[g0 + 1] + b_hh[g0 + 1];

    const int ntiles = nrows / 32;
    int tile = blockIdx.x;
    int buf = 0;

    float4 pre0 = make_float4(0.f, 0.f, 0.f, 0.f), pre1 = pre0;
    if (tile < ntiles) {
        const float4* src = (const float4*)(x + (size_t)tile * 32 * DD);
        pre0 = src[tid]; pre1 = src[tid + 256];
    }

    while (tile < ntiles) {
        ((float4*)xs[buf])[tid] = pre0;
        ((float4*)xs[buf])[tid + 256] = pre1;
        __syncthreads();

        int next = tile + gridDim.x;
        if (next < ntiles) {
            const float4* src = (const float4*)(x + (size_t)next * 32 * DD);
            pre0 = src[tid]; pre1 = src[tid + 256];
        }

        float* dst = g_xg + ((size_t)tile * 32 + half * 16) * NG + g0;
#pragma unroll 2
        for (int r = 0; r < 16; ++r) {
            const ulonglong2* v = (const ulonglong2*)xs[buf][half * 16 + r];
            unsigned long long a0 = 0ull, a1 = 0ull, c0 = 0ull, c1 = 0ull;
#pragma unroll
            for (int j = 0; j < 16; ++j) {
                ulonglong2 h2 = v[j];
                a0 = ffma2(wa[j].x, h2.x, a0);
                a1 = ffma2(wa[j].y, h2.y, a1);
                c0 = ffma2(wb[j].x, h2.x, c0);
                c1 = ffma2(wb[j].y, h2.y, c1);
            }
            *(float2*)(dst + r * NG) =
                make_float2(ba + red2(a0) + red2(a1), bb + red2(c0) + red2(c1));
        }
        buf ^= 1;
        tile = next;
    }
}

// ---------------------------------------------------------------------------
// Kernel 2: recurrence. grid=128, 512 threads = 2 independent 256-thread
// groups (one batch each, own named barrier) -> 4 warps/SMSP.
// Each unit u is served by a QUAD of threads: role in {0:(i,g), 1:(f,o)} x
// kh in {0: h[0..31], 1: h[32..63]}. Each thread: 32-long dot for its 2
// gates (8-deep FFMA2 chains), then shfl.xor(1) k-reduction, then
// shfl.xor(2) role exchange for the cell update. h double-buffered ->
// one named barrier per step. All activations via MUFU tanh.approx.
// ---------------------------------------------------------------------------
__global__ void __launch_bounds__(512, 1)
lstm_rec(const float* __restrict__ w_hh, const float* __restrict__ fc_w,
         const float* __restrict__ fc_b, float* __restrict__ out, int Tn)
{
    __shared__ __align__(16) float hsm[2][2][HH];   // [grp][buf][unit]

    const int tid  = threadIdx.x;
    const int grp  = tid >> 8;          // group = batch within block
    const int lt   = tid & 255;
    const int u    = lt >> 2;           // unit 0..63
    const int role = (lt >> 1) & 1;     // 0: (i,g)   1: (f,o)
    const int kh   = lt & 1;            // k-half of the 64-dot
    const int ga   = u + 64 * role;     // i_u or f_u
    const int gb   = ga + 128;          // g_u or o_u
    const int b    = blockIdx.x * 2 + grp;
    const int barid = grp + 1;

    // half-rows of W_hh (32 floats = 8 ulonglong2 each)
    ulonglong2 wa[8], wb[8];
    {
        const ulonglong2* pwa = (const ulonglong2*)(w_hh + ga * HH + kh * 32);
        const ulonglong2* pwb = (const ulonglong2*)(w_hh + gb * HH + kh * 32);
#pragma unroll
        for (int j = 0; j < 8; ++j) { wa[j] = pwa[j]; wb[j] = pwb[j]; }
    }

    // Bv activation: role0 -> tanh(sb); role1 -> sigm(sb)=0.5*tanh(0.5 sb)+0.5
    const float kb  = role ? 0.5f : 1.f;
    const float sc  = role ? 0.5f : 1.f;
    const float off = role ? 0.5f : 0.f;

    const float* pa = g_xg + (size_t)b * Tn * NG + ga;   // xg for ga; +128 for gb

    // prefetch pipeline, distance 4 (both kh threads load same addrs: broadcast)
    float xa0 = pa[0],          xb0 = pa[128];
    float xa1 = pa[NG],         xb1 = pa[NG + 128];
    float xa2 = pa[2 * NG],     xb2 = pa[2 * NG + 128];
    float xa3 = pa[3 * NG],     xb3 = pa[3 * NG + 128];
    pa += 4 * NG;

    if (lt < 64) { hsm[grp][0][lt] = 0.f; hsm[grp][1][lt] = 0.f; }
    __syncthreads();

    float c = 0.f;   // redundant cell state on all 4 quad threads

    for (int t = 0; t < Tn; ++t) {
        const ulonglong2* hv = (const ulonglong2*)hsm[grp][t & 1] + kh * 8;
        unsigned long long a0 = 0ull, a1 = 0ull, c0 = 0ull, c1 = 0ull;
#pragma unroll
        for (int j = 0; j < 8; ++j) {
            ulonglong2 h2 = hv[j];
            a0 = ffma2(wa[j].x, h2.x, a0);
            a1 = ffma2(wa[j].y, h2.y, a1);
            c0 = ffma2(wb[j].x, h2.x, c0);
            c1 = ffma2(wb[j].y, h2.y, c1);
        }
        float paa = red2(a0) + red2(a1);     // partial dot, gate ga
        float pbb = red2(c0) + red2(c1);     // partial dot, gate gb

        // k-reduction across the kh pair (lane^1)
        float qaa = __shfl_xor_sync(0xFFFFFFFFu, paa, 1);
        float qbb = __shfl_xor_sync(0xFFFFFFFFu, pbb, 1);
        float sa = xa0 + (paa + qaa);
        float sb = xb0 + (pbb + qbb);

        // rotate prefetch; LDG overlaps the epilogue
        xa0 = xa1; xa1 = xa2; xa2 = xa3;
        xb0 = xb1; xb1 = xb2; xb2 = xb3;
        if (t + 4 < Tn) {
            xa3 = pa[0]; xb3 = pa[128];
            pa += NG;
        }

        // activations (MUFU tanh): A = sigmoid(sa) = i (role0) or f (role1)
        float A  = fmaf(0.5f, tanh_ap(0.5f * sa), 0.5f);
        float Bv = fmaf(sc, tanh_ap(kb * sb), off);   // g (role0) or o (role1)
        float p  = A * Bv;                            // role0: i*g
        float send = role ? A : p;                    // role1 sends f, role0 sends i*g
        float recv = __shfl_xor_sync(0xFFFFFFFFu, send, 2);
        float cmul = role ? A : recv;                 // f on all quad threads
        float cadd = role ? recv : p;                 // i*g on all quad threads
        c = fmaf(cmul, c, cadd);                      // identical across quad
        float th = tanh_ap(c);
        if (role == 1 && kh == 0)
            hsm[grp][(t + 1) & 1][u] = Bv * th;       // h = o * tanh(c)

        asm volatile("bar.sync %0, 256;" :: "r"(barid));
    }

    // final FC: out[b, o] = h_last . fc_w[o] + fc_b[o]
    const float* hfin = hsm[grp][Tn & 1];
    if (lt < 8) {
        float s = fc_b[lt];
#pragma unroll
        for (int k = 0; k < HH; ++k) s += hfin[k] * fc_w[lt * HH + k];
        out[b * 8 + lt] = s;
    }
}

extern "C" void kernel_launch(void* const* d_in, const int* in_sizes, int n_in,
                              void* d_out, int out_size) {
    const float* x    = (const float*)d_in[0];
    const float* w_ih = (const float*)d_in[1];
    const float* w_hh = (const float*)d_in[2];
    const float* b_ih = (const float*)d_in[3];
    const float* b_hh = (const float*)d_in[4];
    const float* fc_w = (const float*)d_in[5];
    const float* fc_b = (const float*)d_in[6];
    float* out = (float*)d_out;

    const int B = in_sizes[0] / (TT * DD);   // 256
    const int nrows = B * TT;

    xg_gemm<<<148, 256>>>(x, w_ih, b_ih, b_hh, nrows);
    lstm_rec<<<B / 2, 512>>>(w_hh, fc_w, fc_b, out, TT);
}